// round 3
// baseline (speedup 1.0000x reference)
#include <cuda_runtime.h>
#include <stdint.h>

// reference(x) = (U*S)@Vh from SVD of x == exact SVD reconstruction == x.
// Kernel = pure D2D streaming copy of N*3*3 floats.
//
// R3 refinement: input (37.75MB) + output (37.75MB) < 126MB L2. Use
// streaming (evict-first) stores so output write-allocations don't evict
// the input from L2 between graph replays -> reads become L2 hits, kernel
// bound only by the DRAM write stream.

#define CP_THREADS 256
#define CP_UNROLL  8

__global__ void __launch_bounds__(CP_THREADS) copy_unroll_cs_kernel(
    const float4* __restrict__ src, float4* __restrict__ dst, long long n4)
{
    long long base = (long long)blockIdx.x * (CP_THREADS * CP_UNROLL) + threadIdx.x;

    if (base + (long long)(CP_UNROLL - 1) * CP_THREADS < n4) {
        float4 v[CP_UNROLL];
#pragma unroll
        for (int u = 0; u < CP_UNROLL; u++)
            v[u] = __ldcg(&src[base + (long long)u * CP_THREADS]);  // keep in L2
#pragma unroll
        for (int u = 0; u < CP_UNROLL; u++)
            __stcs(&dst[base + (long long)u * CP_THREADS], v[u]);   // evict-first
    } else {
#pragma unroll
        for (int u = 0; u < CP_UNROLL; u++) {
            long long i = base + (long long)u * CP_THREADS;
            if (i < n4) __stcs(&dst[i], __ldcg(&src[i]));
        }
    }
}

__global__ void __launch_bounds__(256) copy_f_tail_kernel(
    const float* __restrict__ src, float* __restrict__ dst,
    long long start, long long n)
{
    long long i = start + (long long)blockIdx.x * blockDim.x + threadIdx.x;
    if (i < n) dst[i] = src[i];
}

extern "C" void kernel_launch(void* const* d_in, const int* in_sizes, int n_in,
                              void* d_out, int out_size) {
    const float* x = (const float*)d_in[0];
    float* out = (float*)d_out;
    long long n = (long long)in_sizes[0];   // total float elements (N*3*3)

    long long n4 = n / 4;
    if (n4 > 0) {
        long long per_block = (long long)CP_THREADS * CP_UNROLL;
        int blocks = (int)((n4 + per_block - 1) / per_block);
        copy_unroll_cs_kernel<<<blocks, CP_THREADS>>>((const float4*)x, (float4*)out, n4);
    }
    long long tail_start = n4 * 4;
    if (n - tail_start > 0) {
        copy_f_tail_kernel<<<1, 256>>>(x, out, tail_start, n);
    }
}